// round 15
// baseline (speedup 1.0000x reference)
#include <cuda_runtime.h>
#include <cuda_fp16.h>
#include <math.h>
#include <stdint.h>

#define BATCH 8
#define HWD 128
#define C1 128
#define DM 256
#define LSEQ 1024
#define NROWS (BATCH*LSEQ)
#define DSTATE 16
#define HEADDIM 64
#define DINNER 512
#define NHEADS 8
#define CONVDIM 544
#define DINPROJ 1064
#define NPAD_IN 1152
#define NCHUNK 16
#define QCH 64
#define EPSV 1e-5f

typedef __half fp16;

// ---------------- scratch (device globals) ----------------
__device__ fp16  g_imh[(size_t)NROWS*2048];
__device__ fp16  g_w2h[256*2048];
__device__ float g_tok[NROWS*DM];
__device__ fp16  g_th[NROWS*DM];
__device__ fp16  g_inwh[4*NPAD_IN*DM];
__device__ fp16  g_owh[4*DM*DINNER];
__device__ fp16  g_zxh[(size_t)NROWS*DINPROJ];   // in_proj output, fp16
__device__ float g_dtraw[NROWS*NHEADS];          // fp32 side-channel for dt tail
__device__ fp16  g_xbch[(size_t)NROWS*CONVDIM];  // conv1d+silu output (fp16)
__device__ fp16  g_ybufh[(size_t)NROWS*DINNER];  // scan output (fp16)
__device__ fp16  g_gah[(size_t)NROWS*DINNER];
__device__ float g_mproj[NROWS*DM];
__device__ float g_pooled[BATCH*DM];

__device__ __forceinline__ float geluf(float t){ return 0.5f*t*(1.0f+erff(t*0.70710678118654752f)); }
// fast silu: MUFU.EX2 + MUFU.RCP instead of software expf + div
__device__ __forceinline__ float siluf(float t){ return __fdividef(t, 1.0f + __expf(-t)); }

__device__ __forceinline__ float blockReduceSum(float v, float* sred){
  int lane = threadIdx.x & 31, wid = threadIdx.x >> 5;
  #pragma unroll
  for (int o=16;o>0;o>>=1) v += __shfl_xor_sync(0xffffffffu,v,o);
  if (lane==0) sred[wid]=v;
  __syncthreads();
  int nw = (blockDim.x+31)>>5;
  if (threadIdx.x < 32){
    float r = (threadIdx.x < nw) ? sred[threadIdx.x] : 0.f;
    #pragma unroll
    for (int o=16;o>0;o>>=1) r += __shfl_xor_sync(0xffffffffu,r,o);
    if (threadIdx.x==0) sred[0]=r;
  }
  __syncthreads();
  float r = sred[0];
  __syncthreads();
  return r;
}

// ---------------- mma/cp.async helpers ----------------
__device__ __forceinline__ uint32_t smem_u32(const void* p){
  uint32_t a;
  asm("{ .reg .u64 t; cvta.to.shared.u64 t, %1; cvt.u32.u64 %0, t; }" : "=r"(a) : "l"(p));
  return a;
}
__device__ __forceinline__ void ldsm4(uint32_t& a0,uint32_t& a1,uint32_t& a2,uint32_t& a3, uint32_t addr){
  asm volatile("ldmatrix.sync.aligned.m8n8.x4.shared.b16 {%0,%1,%2,%3}, [%4];"
    : "=r"(a0),"=r"(a1),"=r"(a2),"=r"(a3) : "r"(addr));
}
__device__ __forceinline__ void ldsm2(uint32_t& a0,uint32_t& a1, uint32_t addr){
  asm volatile("ldmatrix.sync.aligned.m8n8.x2.shared.b16 {%0,%1}, [%2];"
    : "=r"(a0),"=r"(a1) : "r"(addr));
}
__device__ __forceinline__ void mma16816(float* d, uint32_t a0,uint32_t a1,uint32_t a2,uint32_t a3,
                                         uint32_t b0,uint32_t b1){
  asm volatile("mma.sync.aligned.m16n8k16.row.col.f32.f16.f16.f32 "
    "{%0,%1,%2,%3}, {%4,%5,%6,%7}, {%8,%9}, {%0,%1,%2,%3};"
    : "+f"(d[0]),"+f"(d[1]),"+f"(d[2]),"+f"(d[3])
    : "r"(a0),"r"(a1),"r"(a2),"r"(a3),"r"(b0),"r"(b1));
}
__device__ __forceinline__ void cpasync16(uint32_t s, const void* g){
  asm volatile("cp.async.cg.shared.global [%0], [%1], 16;" :: "r"(s), "l"(g) : "memory");
}
__device__ __forceinline__ void cpcommit(){ asm volatile("cp.async.commit_group;" ::: "memory"); }
__device__ __forceinline__ void cpwait0(){ asm volatile("cp.async.wait_group 0;" ::: "memory"); }
__device__ __forceinline__ void cpwait1(){ asm volatile("cp.async.wait_group 1;" ::: "memory"); }

// ---------------- fp16 HMMA GEMM: C[M,N] = A[M,K] @ B^T ----------------
// epi 0: fp32 C.  epi 1: BN+GELU -> fp32 C + fp16 Cho.  epi 2: fp16 Cho + fp32 dt tail.
#define SPAD 72
#define ABUF (64*SPAD*2)
#define BBUF (128*SPAD*2)
#define STAGEB (ABUF+BBUF)
#define MMG_SMEM (2*STAGEB)
__global__ __launch_bounds__(256) void mmagemm_kernel(
    const fp16* __restrict__ A, const fp16* __restrict__ B,
    float* __restrict__ C, int K, int Nreal, int ldc, int epi,
    const float* __restrict__ eg, const float* __restrict__ eb,
    fp16* __restrict__ Cho)
{
  extern __shared__ char smem[];
  uint32_t sbase = smem_u32(smem);
  int tid = threadIdx.x, lane = tid & 31, wid = tid >> 5;
  int row0 = blockIdx.y<<6, col0 = blockIdx.x<<7;
  int warp_m = wid >> 2, warp_n = wid & 3;
  int m0w = warp_m*32, n0w = warp_n*32;

  int a_r[2], a_c[2];
  #pragma unroll
  for (int j=0;j<2;j++){ int id = tid + j*256; a_r[j]=id>>3; a_c[j]=(id&7)*8; }
  int b_r[4], b_c[4];
  #pragma unroll
  for (int j=0;j<4;j++){ int id = tid + j*256; b_r[j]=id>>3; b_c[j]=(id&7)*8; }

  uint32_t a_ld = (uint32_t)((m0w + (lane&7) + ((lane>>3)&1)*8)*SPAD*2 + (lane>>4)*16);
  uint32_t b_ld = (uint32_t)((n0w + (lane&7))*SPAD*2 + ((lane>>3)&1)*16);

  float d[2][4][4];
  #pragma unroll
  for (int i=0;i<2;i++)
    #pragma unroll
    for (int j=0;j<4;j++)
      #pragma unroll
      for (int q=0;q<4;q++) d[i][j][q]=0.f;

  int NC = K>>6;
  {
    uint32_t sa = sbase, sb = sbase + ABUF;
    #pragma unroll
    for (int j=0;j<2;j++) cpasync16(sa + (uint32_t)(a_r[j]*SPAD + a_c[j])*2,
                                    A + (size_t)(row0+a_r[j])*K + a_c[j]);
    #pragma unroll
    for (int j=0;j<4;j++) cpasync16(sb + (uint32_t)(b_r[j]*SPAD + b_c[j])*2,
                                    B + (size_t)(col0+b_r[j])*K + b_c[j]);
    cpcommit();
  }
  for (int c=0;c<NC;c++){
    if (c+1<NC){
      uint32_t sa = sbase + ((c+1)&1)*STAGEB, sb = sa + ABUF;
      int kof = (c+1)*64;
      #pragma unroll
      for (int j=0;j<2;j++) cpasync16(sa + (uint32_t)(a_r[j]*SPAD + a_c[j])*2,
                                      A + (size_t)(row0+a_r[j])*K + kof + a_c[j]);
      #pragma unroll
      for (int j=0;j<4;j++) cpasync16(sb + (uint32_t)(b_r[j]*SPAD + b_c[j])*2,
                                      B + (size_t)(col0+b_r[j])*K + kof + b_c[j]);
      cpcommit();
      cpwait1();
    } else {
      cpwait0();
    }
    __syncthreads();
    uint32_t uA = sbase + (c&1)*STAGEB;
    uint32_t uB = uA + ABUF;
    #pragma unroll
    for (int kk=0;kk<4;kk++){
      uint32_t b0[4], b1[4];
      #pragma unroll
      for (int j=0;j<4;j++)
        ldsm2(b0[j], b1[j], uB + b_ld + (uint32_t)(j*8*SPAD*2 + kk*32));
      #pragma unroll
      for (int i=0;i<2;i++){
        uint32_t x0,x1,x2,x3;
        ldsm4(x0,x1,x2,x3, uA + a_ld + (uint32_t)(i*16*SPAD*2 + kk*32));
        #pragma unroll
        for (int j=0;j<4;j++) mma16816(d[i][j], x0,x1,x2,x3, b0[j],b1[j]);
      }
    }
    __syncthreads();
  }

  float* stg = (float*)smem;
  #pragma unroll
  for (int i=0;i<2;i++){
    int r0 = m0w + i*16 + (lane>>2);
    #pragma unroll
    for (int j=0;j<4;j++){
      int c0 = n0w + j*8 + (lane&3)*2;
      *(float2*)&stg[r0*132 + c0]     = make_float2(d[i][j][0], d[i][j][1]);
      *(float2*)&stg[(r0+8)*132 + c0] = make_float2(d[i][j][2], d[i][j][3]);
    }
  }
  __syncthreads();

  #pragma unroll 1
  for (int q=0;q<8;q++){
    int e = q*256 + tid;
    int rr = e>>5, cc = (e&31)*4;
    float vx = stg[rr*132+cc+0], vy = stg[rr*132+cc+1];
    float vz = stg[rr*132+cc+2], vw = stg[rr*132+cc+3];
    int gcol = col0 + cc, grow = row0 + rr;
    if (epi==1){
      vx = geluf(vx*eg[gcol+0]+eb[gcol+0]);
      vy = geluf(vy*eg[gcol+1]+eb[gcol+1]);
      vz = geluf(vz*eg[gcol+2]+eb[gcol+2]);
      vw = geluf(vw*eg[gcol+3]+eb[gcol+3]);
      *(float4*)(C + (size_t)grow*ldc + gcol) = make_float4(vx,vy,vz,vw);
      __half2* ph = (__half2*)(Cho + (size_t)grow*ldc + gcol);
      ph[0] = __floats2half2_rn(vx,vy);
      ph[1] = __floats2half2_rn(vz,vw);
    } else if (epi==2){
      if (gcol + 4 <= Nreal){
        __half2* ph = (__half2*)(Cho + (size_t)grow*ldc + gcol);
        ph[0] = __floats2half2_rn(vx,vy);
        ph[1] = __floats2half2_rn(vz,vw);
        if (gcol >= 1056)
          *(float4*)(C + (size_t)grow*8 + (gcol-1056)) = make_float4(vx,vy,vz,vw);
      }
    } else {
      if (gcol < Nreal)
        *(float4*)(C + (size_t)grow*ldc + gcol) = make_float4(vx,vy,vz,vw);
    }
  }
}

// ---------------- weight prep ----------------
__global__ void prep_inw(const float* __restrict__ in_w){
  int idx = blockIdx.x*256 + threadIdx.x;
  int l = idx / (NPAD_IN*DM); int rem = idx % (NPAD_IN*DM);
  int n = rem / DM, k = rem % DM;
  float v = (n < DINPROJ) ? in_w[((size_t)l*DM + k)*DINPROJ + n] : 0.f;
  g_inwh[idx] = __float2half(v);
}
__global__ void prep_outw(const float* __restrict__ out_w){
  int idx = blockIdx.x*256 + threadIdx.x;
  int l = idx / (DM*DINNER); int rem = idx % (DM*DINNER);
  int n = rem / DINNER, k = rem % DINNER;
  g_owh[idx] = __float2half(out_w[((size_t)l*DINNER + k)*DM + n]);
}
__global__ void prep_w2(const float* __restrict__ w2){
  int idx = blockIdx.x*256 + threadIdx.x;
  g_w2h[idx] = __float2half(w2[idx]);
}

// ---------------- fused stem conv1 -> im2col fp16 ----------------
__global__ __launch_bounds__(128) void conv1_kernel(const float* __restrict__ x,
    const float* __restrict__ w, const float* __restrict__ g1, const float* __restrict__ b1)
{
  __shared__ float swv[C1*27];
  __shared__ float sg[C1], sb[C1];
  __shared__ fp16 sstage[32][516];
  int xx = threadIdx.x, y = blockIdx.x, b = blockIdx.y;
  for (int i=xx;i<C1*27;i+=128) swv[i]=w[i];
  sg[xx]=g1[xx]; sb[xx]=b1[xx];
  __syncthreads();
  float in[27];
  int q=0;
  #pragma unroll
  for (int ci=0;ci<3;ci++)
    #pragma unroll
    for (int ky=0;ky<3;ky++){
      int iy=y+ky-1;
      #pragma unroll
      for (int kx=0;kx<3;kx++){
        int ix=xx+kx-1;
        in[q++] = (iy>=0 && iy<HWD && ix>=0 && ix<HWD) ? x[((b*3+ci)*HWD+iy)*HWD+ix] : 0.f;
      }
    }
  int srow = xx>>2, scol = xx&3;
  for (int co=0;co<C1;co++){
    float acc=0.f;
    #pragma unroll
    for (int t=0;t<27;t++) acc += in[t]*swv[co*27+t];
    sstage[srow][co*4+scol] = __float2half(geluf(acc*sg[co]+sb[co]));
  }
  __syncthreads();
  int ky = y & 3;
  size_t rowbase = (size_t)b*LSEQ + (size_t)(y>>2)*32;
  #pragma unroll 4
  for (int t=0;t<32;t++){
    int id = xx + t*128;
    int r = id >> 7, ci = id & 127;
    *(uint2*)(g_imh + (rowbase + r)*2048 + ci*16 + ky*4) = *(uint2*)&sstage[r][ci*4];
  }
}

// ---------------- depthwise conv1d + silu (fp16 in, fp16 out) ----------------
__global__ void dwdt_kernel(const float* __restrict__ cw, const float* __restrict__ cb, int layer){
  int idx = blockIdx.x*256 + threadIdx.x;
  if (idx >= NROWS*CONVDIM) return;
  int c = idx % CONVDIM; int row = idx / CONVDIM;
  int l = row & 1023, b = row >> 10;
  const float* wp = cw + (layer*CONVDIM + c)*4;
  float acc = cb[layer*CONVDIM + c];
  const fp16* zcol = g_zxh + (size_t)(b<<10)*DINPROJ + 512 + c;
  #pragma unroll
  for (int k=0;k<4;k++){
    int ls = l + k - 3;
    if (ls >= 0) acc += __half2float(zcol[(size_t)ls*DINPROJ]) * wp[k];
  }
  g_xbch[(size_t)row*CONVDIM + c] = __float2half(siluf(acc));
}

// ---------------- fused SSM scan: grid 128 = (b,h,phalf), block 512 = (chunk, 32 p) ----------------
// smem: sB fp32 64K | sCh fp16 32K | sXh fp16 64K | sS fp32 32K | sdA 4K | sdt 4K | sAc
#define SCAN_SMEM (65536+32768+65536+32768+4096+4096+64)
__global__ __launch_bounds__(512,1) void scan_fused_kernel(
    const float* __restrict__ dt_bias, const float* __restrict__ A_log,
    const float* __restrict__ Dskip, int layer){
  extern __shared__ char smraw[];
  float* sB  = (float*)smraw;                       // [1024][16] fp32
  fp16*  sCh = (fp16*)(smraw + 65536);              // [1024][16] fp16
  fp16*  sXh = (fp16*)(smraw + 98304);              // [1024][32] fp16
  float* sS  = (float*)(smraw + 163840);            // [16][512]
  float* sdA = (float*)(smraw + 196608);            // [1024]
  float* sdt = (float*)(smraw + 200704);            // [1024]
  float* sAc = (float*)(smraw + 204800);            // [16]

  int tid = threadIdx.x;
  int bh = blockIdx.x >> 1, phalf = blockIdx.x & 1;
  int b = bh>>3, h = bh&7;
  int c = tid>>5, pl = tid&31;
  int p = phalf*32 + pl;

  const fp16* xbase = g_xbch + (size_t)b*LSEQ*CONVDIM;

  // stage dt/dA (fast-math intrinsics)
  float aexp = __expf(A_log[layer*NHEADS+h]);
  float dtb  = dt_bias[layer*NHEADS+h];
  #pragma unroll
  for (int j=0;j<2;j++){
    int l = tid + j*512;
    float raw = g_dtraw[((size_t)b*LSEQ + l)*NHEADS + h] + dtb;
    float dt = (raw > 20.f) ? raw : __logf(1.0f + __expf(raw));
    sdt[l] = dt;
    sdA[l] = __expf(-aexp*dt);
  }
  // stage B (fp32), C (fp16): coalesced row-segment loads
  #pragma unroll
  for (int j=0;j<32;j++){
    int id = tid + j*512;
    int l = id>>4, n = id&15;
    sB[id]  = __half2float(xbase[(size_t)l*CONVDIM + DINNER + n]);
    sCh[id] = xbase[(size_t)l*CONVDIM + DINNER + DSTATE + n];
  }
  // stage x (fp16) by pure copy: 32 channels of this block, coalesced 64B/row
  {
    int chbase = h*HEADDIM + phalf*32;
    #pragma unroll
    for (int j=0;j<64;j++){
      int id = tid + j*512;
      int l = id>>5, pw = id&31;
      sXh[l*32 + pw] = xbase[(size_t)l*CONVDIM + chbase + pw];
    }
  }
  __syncthreads();

  if (pl == 0){
    float r = 1.f;
    #pragma unroll 4
    for (int s=0;s<QCH;s++) r *= sdA[c*QCH+s];
    sAc[c] = r;
  }

  int l0 = c*QCH;

  // Phase A: local scan from zero (states only)
  float hr[DSTATE];
  #pragma unroll
  for (int n=0;n<DSTATE;n++) hr[n]=0.f;
  #pragma unroll 4
  for (int s=0;s<QCH;s++){
    int l = l0+s;
    float xs = __half2float(sXh[l*32 + pl]);
    float xv = xs * sdt[l];
    float dAv = sdA[l];
    const float4* Bv = (const float4*)&sB[l*DSTATE];
    float4 b0=Bv[0], b1=Bv[1], b2=Bv[2], b3=Bv[3];
    hr[0]=hr[0]*dAv+xv*b0.x;  hr[1]=hr[1]*dAv+xv*b0.y;
    hr[2]=hr[2]*dAv+xv*b0.z;  hr[3]=hr[3]*dAv+xv*b0.w;
    hr[4]=hr[4]*dAv+xv*b1.x;  hr[5]=hr[5]*dAv+xv*b1.y;
    hr[6]=hr[6]*dAv+xv*b1.z;  hr[7]=hr[7]*dAv+xv*b1.w;
    hr[8]=hr[8]*dAv+xv*b2.x;  hr[9]=hr[9]*dAv+xv*b2.y;
    hr[10]=hr[10]*dAv+xv*b2.z;hr[11]=hr[11]*dAv+xv*b2.w;
    hr[12]=hr[12]*dAv+xv*b3.x;hr[13]=hr[13]*dAv+xv*b3.y;
    hr[14]=hr[14]*dAv+xv*b3.z;hr[15]=hr[15]*dAv+xv*b3.w;
  }
  #pragma unroll
  for (int n=0;n<DSTATE;n++) sS[c*512 + n*32 + pl] = hr[n];
  __syncthreads();

  // Phase B: chunk prefix combine (512 slices, 512 threads)
  {
    float run = 0.f;
    #pragma unroll
    for (int c2=0;c2<NCHUNK;c2++){
      float tmp = sS[c2*512 + tid];
      sS[c2*512 + tid] = run;
      run = run*sAc[c2] + tmp;
    }
  }
  __syncthreads();

  // Phase C: re-scan from correct start state, emit y (fp16)
  #pragma unroll
  for (int n=0;n<DSTATE;n++) hr[n] = sS[c*512 + n*32 + pl];
  float Dh = Dskip[layer*NHEADS+h];
  fp16* yp = g_ybufh + ((size_t)b*LSEQ + l0)*DINNER + h*HEADDIM + p;
  #pragma unroll 2
  for (int s=0;s<QCH;s++){
    int l = l0+s;
    float xs = __half2float(sXh[l*32 + pl]);
    float xv = xs * sdt[l];
    float dAv = sdA[l];
    const float4* Bv = (const float4*)&sB[l*DSTATE];
    const __half2* Ch = (const __half2*)&sCh[l*DSTATE];
    float4 b0=Bv[0], b1=Bv[1], b2=Bv[2], b3=Bv[3];
    float2 c0=__half22float2(Ch[0]), c1=__half22float2(Ch[1]);
    float2 c2v=__half22float2(Ch[2]), c3=__half22float2(Ch[3]);
    float2 c4=__half22float2(Ch[4]), c5=__half22float2(Ch[5]);
    float2 c6=__half22float2(Ch[6]), c7=__half22float2(Ch[7]);
    float y = xs*Dh;
    hr[0]=hr[0]*dAv+xv*b0.x;   y+=hr[0]*c0.x;
    hr[1]=hr[1]*dAv+xv*b0.y;   y+=hr[1]*c0.y;
    hr[2]=hr[2]*dAv+xv*b0.z;   y+=hr[2]*c1.x;
    hr[3]=hr[3]*dAv+xv*b0.w;   y+=hr[3]*c1.y;
    hr[4]=hr[4]*dAv+xv*b1.x;   y+=hr[4]*c2v.x;
    hr[5]=hr[5]*dAv+xv*b1.y;   y+=hr[5]*c2v.y;
    hr[6]=hr[6]*dAv+xv*b1.z;   y+=hr[6]*c3.x;
    hr[7]=hr[7]*dAv+xv*b1.w;   y+=hr[7]*c3.y;
    hr[8]=hr[8]*dAv+xv*b2.x;   y+=hr[8]*c4.x;
    hr[9]=hr[9]*dAv+xv*b2.y;   y+=hr[9]*c4.y;
    hr[10]=hr[10]*dAv+xv*b2.z; y+=hr[10]*c5.x;
    hr[11]=hr[11]*dAv+xv*b2.w; y+=hr[11]*c5.y;
    hr[12]=hr[12]*dAv+xv*b3.x; y+=hr[12]*c6.x;
    hr[13]=hr[13]*dAv+xv*b3.y; y+=hr[13]*c6.y;
    hr[14]=hr[14]*dAv+xv*b3.z; y+=hr[14]*c7.x;
    hr[15]=hr[15]*dAv+xv*b3.w; y+=hr[15]*c7.y;
    yp[(size_t)s*DINNER] = __float2half(y);
  }
}

// ---------------- gate + RMS-norm -> fp16 ----------------
__global__ __launch_bounds__(128) void gate_kernel(const float* __restrict__ rms_w, int layer){
  __shared__ float sred[32];
  size_t row = blockIdx.x;
  int tid = threadIdx.x;
  float v[4]; float ss = 0.f;
  #pragma unroll
  for (int j=0;j<4;j++){
    int d = tid + j*128;
    float z = __half2float(g_zxh[row*DINPROJ + d]);
    float yv = __half2float(g_ybufh[row*DINNER + d]);
    float g = yv * siluf(z);
    v[j]=g; ss += g*g;
  }
  ss = blockReduceSum(ss, sred);
  float rstd = rsqrtf(ss*(1.0f/DINNER) + EPSV);
  #pragma unroll
  for (int j=0;j<4;j++){
    int d = tid + j*128;
    g_gah[row*DINNER + d] = __float2half(v[j]*rstd*rms_w[layer*DINNER + d]);
  }
}

// ---------------- residual + LayerNorm -> tok fp32 + fp16 ----------------
__global__ __launch_bounds__(256) void lnres_kernel(const float* __restrict__ lg, const float* __restrict__ lb, int layer){
  __shared__ float sred[32];
  size_t row = blockIdx.x; int d = threadIdx.x;
  float v = g_mproj[row*DM + d] + g_tok[row*DM + d];
  float mean = blockReduceSum(v, sred) * (1.0f/DM);
  float dv = v - mean;
  float var = blockReduceSum(dv*dv, sred) * (1.0f/DM);
  float o = dv*rsqrtf(var+EPSV)*lg[layer*DM+d] + lb[layer*DM+d];
  g_tok[row*DM + d] = o;
  g_th[row*DM + d] = __float2half(o);
}

// ---------------- grid-wide mean pool over L ----------------
__global__ __launch_bounds__(256) void pool_kernel(){
  __shared__ float s[256];
  int b = blockIdx.x >> 5, cg = blockIdx.x & 31;
  int colq = threadIdx.x & 7, lg = threadIdx.x >> 3;
  int col = cg*8 + colq;
  float acc = 0.f;
  for (int j=0;j<32;j++){
    int l = lg + j*32;
    acc += g_tok[((size_t)b*LSEQ + l)*DM + col];
  }
  s[threadIdx.x] = acc;
  __syncthreads();
  for (int off=16; off>0; off>>=1){
    if (lg < off) s[lg*8+colq] += s[(lg+off)*8+colq];
    __syncthreads();
  }
  if (lg == 0) g_pooled[b*DM + col] = s[colq]*(1.0f/LSEQ);
}

// ---------------- LN + head ----------------
__global__ __launch_bounds__(256) void head_kernel(const float* __restrict__ hg, const float* __restrict__ hb,
    const float* __restrict__ hw, const float* __restrict__ hbias, float* __restrict__ out){
  __shared__ float sred[32];
  __shared__ float sn[DM];
  int b = blockIdx.x, d = threadIdx.x;
  float pooled = g_pooled[b*DM + d];
  float mean = blockReduceSum(pooled, sred)*(1.0f/DM);
  float dv = pooled-mean;
  float var = blockReduceSum(dv*dv, sred)*(1.0f/DM);
  sn[d] = dv*rsqrtf(var+EPSV)*hg[d]+hb[d];
  __syncthreads();
  if (d < 10){
    float acc = hbias[d];
    for (int k=0;k<DM;k++) acc += sn[k]*hw[k*10+d];
    out[b*10+d] = acc;
  }
}

// ---------------- host launcher ----------------
extern "C" void kernel_launch(void* const* d_in, const int* in_sizes, int n_in,
                              void* d_out, int out_size)
{
  const float* x       = (const float*)d_in[0];
  const float* w1      = (const float*)d_in[1];
  const float* sg1     = (const float*)d_in[2];
  const float* sb1     = (const float*)d_in[3];
  const float* w2      = (const float*)d_in[4];
  const float* sg2     = (const float*)d_in[5];
  const float* sb2     = (const float*)d_in[6];
  const float* in_w    = (const float*)d_in[7];
  const float* conv_w  = (const float*)d_in[8];
  const float* conv_b  = (const float*)d_in[9];
  const float* dt_bias = (const float*)d_in[10];
  const float* A_log   = (const float*)d_in[11];
  const float* D_skip  = (const float*)d_in[12];
  const float* rms_w   = (const float*)d_in[13];
  const float* out_w   = (const float*)d_in[14];
  const float* ln_g    = (const float*)d_in[15];
  const float* ln_b    = (const float*)d_in[16];
  const float* hg      = (const float*)d_in[17];
  const float* hb      = (const float*)d_in[18];
  const float* hw      = (const float*)d_in[19];
  const float* hbias   = (const float*)d_in[20];
  float* out = (float*)d_out;

  cudaFuncSetAttribute(mmagemm_kernel, cudaFuncAttributeMaxDynamicSharedMemorySize, MMG_SMEM);
  cudaFuncSetAttribute(scan_fused_kernel, cudaFuncAttributeMaxDynamicSharedMemorySize, SCAN_SMEM);

  void *p;
  cudaGetSymbolAddress(&p, g_imh);   fp16* p_imh = (fp16*)p;
  cudaGetSymbolAddress(&p, g_w2h);   fp16* p_w2h = (fp16*)p;
  cudaGetSymbolAddress(&p, g_tok);   float* p_tok = (float*)p;
  cudaGetSymbolAddress(&p, g_th);    fp16* p_th = (fp16*)p;
  cudaGetSymbolAddress(&p, g_inwh);  fp16* p_inwh = (fp16*)p;
  cudaGetSymbolAddress(&p, g_owh);   fp16* p_owh = (fp16*)p;
  cudaGetSymbolAddress(&p, g_zxh);   fp16* p_zxh = (fp16*)p;
  cudaGetSymbolAddress(&p, g_dtraw); float* p_dtraw = (float*)p;
  cudaGetSymbolAddress(&p, g_gah);   fp16* p_gah = (fp16*)p;
  cudaGetSymbolAddress(&p, g_mproj); float* p_m = (float*)p;

  // preps first so the ncu capture index lands on an in-loop kernel
  prep_inw<<<(4*NPAD_IN*DM)/256,256>>>(in_w);
  prep_outw<<<(4*DM*DINNER)/256,256>>>(out_w);
  prep_w2<<<(256*2048)/256,256>>>(w2);
  conv1_kernel<<<dim3(HWD,BATCH),128>>>(x, w1, sg1, sb1);

  mmagemm_kernel<<<dim3(2,128),256,MMG_SMEM>>>(p_imh, p_w2h,
      p_tok, 2048, 256, 256, 1, sg2, sb2, p_th);

  for (int i=0;i<4;i++){
    mmagemm_kernel<<<dim3(9,128),256,MMG_SMEM>>>(p_th,
        p_inwh + (size_t)i*NPAD_IN*DM,
        p_dtraw, DM, DINPROJ, DINPROJ, 2, (const float*)0, (const float*)0, p_zxh);
    dwdt_kernel<<<(NROWS*CONVDIM+255)/256,256>>>(conv_w, conv_b, i);
    scan_fused_kernel<<<128,512,SCAN_SMEM>>>(dt_bias, A_log, D_skip, i);
    gate_kernel<<<NROWS,128>>>(rms_w, i);
    mmagemm_kernel<<<dim3(2,128),256,MMG_SMEM>>>(p_gah,
        p_owh + (size_t)i*DM*DINNER,
        p_m, DINNER, DM, DM, 0, (const float*)0, (const float*)0, (fp16*)0);
    lnres_kernel<<<NROWS,256>>>(ln_g, ln_b, i);
  }

  pool_kernel<<<BATCH*32,256>>>();
  head_kernel<<<BATCH,256>>>(hg, hb, hw, hbias, out);
}

// round 16
// speedup vs baseline: 1.0566x; 1.0566x over previous
#include <cuda_runtime.h>
#include <cuda_fp16.h>
#include <math.h>
#include <stdint.h>

#define BATCH 8
#define HWD 128
#define C1 128
#define DM 256
#define LSEQ 1024
#define NROWS (BATCH*LSEQ)
#define DSTATE 16
#define HEADDIM 64
#define DINNER 512
#define NHEADS 8
#define CONVDIM 544
#define DINPROJ 1064
#define NPAD_IN 1152
#define NCHUNK 16
#define QCH 64
#define EPSV 1e-5f

typedef __half fp16;

// ---------------- scratch (device globals) ----------------
__device__ fp16  g_imh[(size_t)NROWS*2048];
__device__ fp16  g_w2h[256*2048];
__device__ float g_tok[NROWS*DM];
__device__ fp16  g_th[NROWS*DM];
__device__ fp16  g_inwh[4*NPAD_IN*DM];
__device__ fp16  g_owh[4*DM*DINNER];
__device__ fp16  g_zxh[(size_t)NROWS*DINPROJ];   // in_proj output, fp16
__device__ float g_dtraw[NROWS*NHEADS];          // fp32 side-channel for dt tail
__device__ fp16  g_xbch[(size_t)NROWS*CONVDIM];  // conv1d+silu output (fp16)
__device__ fp16  g_ybufh[(size_t)NROWS*DINNER];  // scan output (fp16)
__device__ fp16  g_gah[(size_t)NROWS*DINNER];
__device__ float g_mproj[NROWS*DM];
__device__ float g_pooled[BATCH*DM];

__device__ __forceinline__ float geluf(float t){ return 0.5f*t*(1.0f+erff(t*0.70710678118654752f)); }
__device__ __forceinline__ float siluf(float t){ return __fdividef(t, 1.0f + __expf(-t)); }

__device__ __forceinline__ float blockReduceSum(float v, float* sred){
  int lane = threadIdx.x & 31, wid = threadIdx.x >> 5;
  #pragma unroll
  for (int o=16;o>0;o>>=1) v += __shfl_xor_sync(0xffffffffu,v,o);
  if (lane==0) sred[wid]=v;
  __syncthreads();
  int nw = (blockDim.x+31)>>5;
  if (threadIdx.x < 32){
    float r = (threadIdx.x < nw) ? sred[threadIdx.x] : 0.f;
    #pragma unroll
    for (int o=16;o>0;o>>=1) r += __shfl_xor_sync(0xffffffffu,r,o);
    if (threadIdx.x==0) sred[0]=r;
  }
  __syncthreads();
  float r = sred[0];
  __syncthreads();
  return r;
}

// ---------------- mma/cp.async helpers ----------------
__device__ __forceinline__ uint32_t smem_u32(const void* p){
  uint32_t a;
  asm("{ .reg .u64 t; cvta.to.shared.u64 t, %1; cvt.u32.u64 %0, t; }" : "=r"(a) : "l"(p));
  return a;
}
__device__ __forceinline__ void ldsm4(uint32_t& a0,uint32_t& a1,uint32_t& a2,uint32_t& a3, uint32_t addr){
  asm volatile("ldmatrix.sync.aligned.m8n8.x4.shared.b16 {%0,%1,%2,%3}, [%4];"
    : "=r"(a0),"=r"(a1),"=r"(a2),"=r"(a3) : "r"(addr));
}
__device__ __forceinline__ void ldsm2(uint32_t& a0,uint32_t& a1, uint32_t addr){
  asm volatile("ldmatrix.sync.aligned.m8n8.x2.shared.b16 {%0,%1}, [%2];"
    : "=r"(a0),"=r"(a1) : "r"(addr));
}
__device__ __forceinline__ void mma16816(float* d, uint32_t a0,uint32_t a1,uint32_t a2,uint32_t a3,
                                         uint32_t b0,uint32_t b1){
  asm volatile("mma.sync.aligned.m16n8k16.row.col.f32.f16.f16.f32 "
    "{%0,%1,%2,%3}, {%4,%5,%6,%7}, {%8,%9}, {%0,%1,%2,%3};"
    : "+f"(d[0]),"+f"(d[1]),"+f"(d[2]),"+f"(d[3])
    : "r"(a0),"r"(a1),"r"(a2),"r"(a3),"r"(b0),"r"(b1));
}
__device__ __forceinline__ void cpasync16(uint32_t s, const void* g){
  asm volatile("cp.async.cg.shared.global [%0], [%1], 16;" :: "r"(s), "l"(g) : "memory");
}
__device__ __forceinline__ void cpcommit(){ asm volatile("cp.async.commit_group;" ::: "memory"); }
__device__ __forceinline__ void cpwait0(){ asm volatile("cp.async.wait_group 0;" ::: "memory"); }
__device__ __forceinline__ void cpwait1(){ asm volatile("cp.async.wait_group 1;" ::: "memory"); }

// ---------------- fp16 HMMA GEMM: C[M,N] = A[M,K] @ B^T ----------------
#define SPAD 72
#define ABUF (64*SPAD*2)
#define BBUF (128*SPAD*2)
#define STAGEB (ABUF+BBUF)
#define MMG_SMEM (2*STAGEB)
__global__ __launch_bounds__(256) void mmagemm_kernel(
    const fp16* __restrict__ A, const fp16* __restrict__ B,
    float* __restrict__ C, int K, int Nreal, int ldc, int epi,
    const float* __restrict__ eg, const float* __restrict__ eb,
    fp16* __restrict__ Cho)
{
  extern __shared__ char smem[];
  uint32_t sbase = smem_u32(smem);
  int tid = threadIdx.x, lane = tid & 31, wid = tid >> 5;
  int row0 = blockIdx.y<<6, col0 = blockIdx.x<<7;
  int warp_m = wid >> 2, warp_n = wid & 3;
  int m0w = warp_m*32, n0w = warp_n*32;

  int a_r[2], a_c[2];
  #pragma unroll
  for (int j=0;j<2;j++){ int id = tid + j*256; a_r[j]=id>>3; a_c[j]=(id&7)*8; }
  int b_r[4], b_c[4];
  #pragma unroll
  for (int j=0;j<4;j++){ int id = tid + j*256; b_r[j]=id>>3; b_c[j]=(id&7)*8; }

  uint32_t a_ld = (uint32_t)((m0w + (lane&7) + ((lane>>3)&1)*8)*SPAD*2 + (lane>>4)*16);
  uint32_t b_ld = (uint32_t)((n0w + (lane&7))*SPAD*2 + ((lane>>3)&1)*16);

  float d[2][4][4];
  #pragma unroll
  for (int i=0;i<2;i++)
    #pragma unroll
    for (int j=0;j<4;j++)
      #pragma unroll
      for (int q=0;q<4;q++) d[i][j][q]=0.f;

  int NC = K>>6;
  {
    uint32_t sa = sbase, sb = sbase + ABUF;
    #pragma unroll
    for (int j=0;j<2;j++) cpasync16(sa + (uint32_t)(a_r[j]*SPAD + a_c[j])*2,
                                    A + (size_t)(row0+a_r[j])*K + a_c[j]);
    #pragma unroll
    for (int j=0;j<4;j++) cpasync16(sb + (uint32_t)(b_r[j]*SPAD + b_c[j])*2,
                                    B + (size_t)(col0+b_r[j])*K + b_c[j]);
    cpcommit();
  }
  for (int c=0;c<NC;c++){
    if (c+1<NC){
      uint32_t sa = sbase + ((c+1)&1)*STAGEB, sb = sa + ABUF;
      int kof = (c+1)*64;
      #pragma unroll
      for (int j=0;j<2;j++) cpasync16(sa + (uint32_t)(a_r[j]*SPAD + a_c[j])*2,
                                      A + (size_t)(row0+a_r[j])*K + kof + a_c[j]);
      #pragma unroll
      for (int j=0;j<4;j++) cpasync16(sb + (uint32_t)(b_r[j]*SPAD + b_c[j])*2,
                                      B + (size_t)(col0+b_r[j])*K + kof + b_c[j]);
      cpcommit();
      cpwait1();
    } else {
      cpwait0();
    }
    __syncthreads();
    uint32_t uA = sbase + (c&1)*STAGEB;
    uint32_t uB = uA + ABUF;
    #pragma unroll
    for (int kk=0;kk<4;kk++){
      uint32_t b0[4], b1[4];
      #pragma unroll
      for (int j=0;j<4;j++)
        ldsm2(b0[j], b1[j], uB + b_ld + (uint32_t)(j*8*SPAD*2 + kk*32));
      #pragma unroll
      for (int i=0;i<2;i++){
        uint32_t x0,x1,x2,x3;
        ldsm4(x0,x1,x2,x3, uA + a_ld + (uint32_t)(i*16*SPAD*2 + kk*32));
        #pragma unroll
        for (int j=0;j<4;j++) mma16816(d[i][j], x0,x1,x2,x3, b0[j],b1[j]);
      }
    }
    __syncthreads();
  }

  float* stg = (float*)smem;
  #pragma unroll
  for (int i=0;i<2;i++){
    int r0 = m0w + i*16 + (lane>>2);
    #pragma unroll
    for (int j=0;j<4;j++){
      int c0 = n0w + j*8 + (lane&3)*2;
      *(float2*)&stg[r0*132 + c0]     = make_float2(d[i][j][0], d[i][j][1]);
      *(float2*)&stg[(r0+8)*132 + c0] = make_float2(d[i][j][2], d[i][j][3]);
    }
  }
  __syncthreads();

  #pragma unroll 1
  for (int q=0;q<8;q++){
    int e = q*256 + tid;
    int rr = e>>5, cc = (e&31)*4;
    float vx = stg[rr*132+cc+0], vy = stg[rr*132+cc+1];
    float vz = stg[rr*132+cc+2], vw = stg[rr*132+cc+3];
    int gcol = col0 + cc, grow = row0 + rr;
    if (epi==1){
      vx = geluf(vx*eg[gcol+0]+eb[gcol+0]);
      vy = geluf(vy*eg[gcol+1]+eb[gcol+1]);
      vz = geluf(vz*eg[gcol+2]+eb[gcol+2]);
      vw = geluf(vw*eg[gcol+3]+eb[gcol+3]);
      *(float4*)(C + (size_t)grow*ldc + gcol) = make_float4(vx,vy,vz,vw);
      __half2* ph = (__half2*)(Cho + (size_t)grow*ldc + gcol);
      ph[0] = __floats2half2_rn(vx,vy);
      ph[1] = __floats2half2_rn(vz,vw);
    } else if (epi==2){
      if (gcol + 4 <= Nreal){
        __half2* ph = (__half2*)(Cho + (size_t)grow*ldc + gcol);
        ph[0] = __floats2half2_rn(vx,vy);
        ph[1] = __floats2half2_rn(vz,vw);
        if (gcol >= 1056)
          *(float4*)(C + (size_t)grow*8 + (gcol-1056)) = make_float4(vx,vy,vz,vw);
      }
    } else {
      if (gcol < Nreal)
        *(float4*)(C + (size_t)grow*ldc + gcol) = make_float4(vx,vy,vz,vw);
    }
  }
}

// ---------------- weight prep ----------------
__global__ void prep_inw(const float* __restrict__ in_w){
  int idx = blockIdx.x*256 + threadIdx.x;
  int l = idx / (NPAD_IN*DM); int rem = idx % (NPAD_IN*DM);
  int n = rem / DM, k = rem % DM;
  float v = (n < DINPROJ) ? in_w[((size_t)l*DM + k)*DINPROJ + n] : 0.f;
  g_inwh[idx] = __float2half(v);
}
__global__ void prep_outw(const float* __restrict__ out_w){
  int idx = blockIdx.x*256 + threadIdx.x;
  int l = idx / (DM*DINNER); int rem = idx % (DM*DINNER);
  int n = rem / DINNER, k = rem % DINNER;
  g_owh[idx] = __float2half(out_w[((size_t)l*DINNER + k)*DM + n]);
}
__global__ void prep_w2(const float* __restrict__ w2){
  int idx = blockIdx.x*256 + threadIdx.x;
  g_w2h[idx] = __float2half(w2[idx]);
}

// ---------------- fused stem conv1 -> im2col fp16 (256 thr: 128 x-pos x 2 ch-halves) ----------------
__global__ __launch_bounds__(256) void conv1_kernel(const float* __restrict__ x,
    const float* __restrict__ w, const float* __restrict__ g1, const float* __restrict__ b1)
{
  __shared__ float swv[C1*27];
  __shared__ float sg[C1], sb[C1];
  __shared__ fp16 sstage[32][516];
  int tid = threadIdx.x;
  int xx = tid & 127, half = tid >> 7;
  int y = blockIdx.x, b = blockIdx.y;
  for (int i=tid;i<C1*27;i+=256) swv[i]=w[i];
  if (tid < C1){ sg[tid]=g1[tid]; sb[tid]=b1[tid]; }
  __syncthreads();
  float in[27];
  int q=0;
  #pragma unroll
  for (int ci=0;ci<3;ci++)
    #pragma unroll
    for (int ky=0;ky<3;ky++){
      int iy=y+ky-1;
      #pragma unroll
      for (int kx=0;kx<3;kx++){
        int ix=xx+kx-1;
        in[q++] = (iy>=0 && iy<HWD && ix>=0 && ix<HWD) ? x[((b*3+ci)*HWD+iy)*HWD+ix] : 0.f;
      }
    }
  int srow = xx>>2, scol = xx&3;
  int co0 = half*64;
  #pragma unroll 4
  for (int co=co0;co<co0+64;co++){
    float acc=0.f;
    #pragma unroll
    for (int t=0;t<27;t++) acc += in[t]*swv[co*27+t];
    sstage[srow][co*4+scol] = __float2half(geluf(acc*sg[co]+sb[co]));
  }
  __syncthreads();
  int ky = y & 3;
  size_t rowbase = (size_t)b*LSEQ + (size_t)(y>>2)*32;
  #pragma unroll 4
  for (int t=0;t<16;t++){
    int id = tid + t*256;           // 0..4095
    int r = id >> 7, ci = id & 127;
    *(uint2*)(g_imh + (rowbase + r)*2048 + ci*16 + ky*4) = *(uint2*)&sstage[r][ci*4];
  }
}

// ---------------- depthwise conv1d + silu (fp16 in, fp16 out) ----------------
__global__ void dwdt_kernel(const float* __restrict__ cw, const float* __restrict__ cb, int layer){
  int idx = blockIdx.x*256 + threadIdx.x;
  if (idx >= NROWS*CONVDIM) return;
  int c = idx % CONVDIM; int row = idx / CONVDIM;
  int l = row & 1023, b = row >> 10;
  const float* wp = cw + (layer*CONVDIM + c)*4;
  float acc = cb[layer*CONVDIM + c];
  const fp16* zcol = g_zxh + (size_t)(b<<10)*DINPROJ + 512 + c;
  #pragma unroll
  for (int k=0;k<4;k++){
    int ls = l + k - 3;
    if (ls >= 0) acc += __half2float(zcol[(size_t)ls*DINPROJ]) * wp[k];
  }
  g_xbch[(size_t)row*CONVDIM + c] = __float2half(siluf(acc));
}

// ---------------- fused SSM scan: grid 128 = (b,h,phalf), block 512 = (chunk, 32 p) ----------------
#define SCAN_SMEM (65536+32768+65536+32768+4096+4096+64)
__global__ __launch_bounds__(512,1) void scan_fused_kernel(
    const float* __restrict__ dt_bias, const float* __restrict__ A_log,
    const float* __restrict__ Dskip, int layer){
  extern __shared__ char smraw[];
  float* sB  = (float*)smraw;                       // [1024][16] fp32
  fp16*  sCh = (fp16*)(smraw + 65536);              // [1024][16] fp16
  fp16*  sXh = (fp16*)(smraw + 98304);              // [1024][32] fp16
  float* sS  = (float*)(smraw + 163840);            // [16][512]
  float* sdA = (float*)(smraw + 196608);            // [1024]
  float* sdt = (float*)(smraw + 200704);            // [1024]
  float* sAc = (float*)(smraw + 204800);            // [16]

  int tid = threadIdx.x;
  int bh = blockIdx.x >> 1, phalf = blockIdx.x & 1;
  int b = bh>>3, h = bh&7;
  int c = tid>>5, pl = tid&31;
  int p = phalf*32 + pl;

  const fp16* xbase = g_xbch + (size_t)b*LSEQ*CONVDIM;

  float aexp = __expf(A_log[layer*NHEADS+h]);
  float dtb  = dt_bias[layer*NHEADS+h];
  #pragma unroll
  for (int j=0;j<2;j++){
    int l = tid + j*512;
    float raw = g_dtraw[((size_t)b*LSEQ + l)*NHEADS + h] + dtb;
    float dt = (raw > 20.f) ? raw : __logf(1.0f + __expf(raw));
    sdt[l] = dt;
    sdA[l] = __expf(-aexp*dt);
  }
  #pragma unroll
  for (int j=0;j<32;j++){
    int id = tid + j*512;
    int l = id>>4, n = id&15;
    sB[id]  = __half2float(xbase[(size_t)l*CONVDIM + DINNER + n]);
    sCh[id] = xbase[(size_t)l*CONVDIM + DINNER + DSTATE + n];
  }
  {
    int chbase = h*HEADDIM + phalf*32;
    #pragma unroll
    for (int j=0;j<64;j++){
      int id = tid + j*512;
      int l = id>>5, pw = id&31;
      sXh[l*32 + pw] = xbase[(size_t)l*CONVDIM + chbase + pw];
    }
  }
  __syncthreads();

  if (pl == 0){
    float r = 1.f;
    #pragma unroll 4
    for (int s=0;s<QCH;s++) r *= sdA[c*QCH+s];
    sAc[c] = r;
  }

  int l0 = c*QCH;

  float hr[DSTATE];
  #pragma unroll
  for (int n=0;n<DSTATE;n++) hr[n]=0.f;
  #pragma unroll 4
  for (int s=0;s<QCH;s++){
    int l = l0+s;
    float xs = __half2float(sXh[l*32 + pl]);
    float xv = xs * sdt[l];
    float dAv = sdA[l];
    const float4* Bv = (const float4*)&sB[l*DSTATE];
    float4 b0=Bv[0], b1=Bv[1], b2=Bv[2], b3=Bv[3];
    hr[0]=hr[0]*dAv+xv*b0.x;  hr[1]=hr[1]*dAv+xv*b0.y;
    hr[2]=hr[2]*dAv+xv*b0.z;  hr[3]=hr[3]*dAv+xv*b0.w;
    hr[4]=hr[4]*dAv+xv*b1.x;  hr[5]=hr[5]*dAv+xv*b1.y;
    hr[6]=hr[6]*dAv+xv*b1.z;  hr[7]=hr[7]*dAv+xv*b1.w;
    hr[8]=hr[8]*dAv+xv*b2.x;  hr[9]=hr[9]*dAv+xv*b2.y;
    hr[10]=hr[10]*dAv+xv*b2.z;hr[11]=hr[11]*dAv+xv*b2.w;
    hr[12]=hr[12]*dAv+xv*b3.x;hr[13]=hr[13]*dAv+xv*b3.y;
    hr[14]=hr[14]*dAv+xv*b3.z;hr[15]=hr[15]*dAv+xv*b3.w;
  }
  #pragma unroll
  for (int n=0;n<DSTATE;n++) sS[c*512 + n*32 + pl] = hr[n];
  __syncthreads();

  {
    float run = 0.f;
    #pragma unroll
    for (int c2=0;c2<NCHUNK;c2++){
      float tmp = sS[c2*512 + tid];
      sS[c2*512 + tid] = run;
      run = run*sAc[c2] + tmp;
    }
  }
  __syncthreads();

  #pragma unroll
  for (int n=0;n<DSTATE;n++) hr[n] = sS[c*512 + n*32 + pl];
  float Dh = Dskip[layer*NHEADS+h];
  fp16* yp = g_ybufh + ((size_t)b*LSEQ + l0)*DINNER + h*HEADDIM + p;
  #pragma unroll 2
  for (int s=0;s<QCH;s++){
    int l = l0+s;
    float xs = __half2float(sXh[l*32 + pl]);
    float xv = xs * sdt[l];
    float dAv = sdA[l];
    const float4* Bv = (const float4*)&sB[l*DSTATE];
    const __half2* Ch = (const __half2*)&sCh[l*DSTATE];
    float4 b0=Bv[0], b1=Bv[1], b2=Bv[2], b3=Bv[3];
    float2 c0=__half22float2(Ch[0]), c1=__half22float2(Ch[1]);
    float2 c2v=__half22float2(Ch[2]), c3=__half22float2(Ch[3]);
    float2 c4=__half22float2(Ch[4]), c5=__half22float2(Ch[5]);
    float2 c6=__half22float2(Ch[6]), c7=__half22float2(Ch[7]);
    float y = xs*Dh;
    hr[0]=hr[0]*dAv+xv*b0.x;   y+=hr[0]*c0.x;
    hr[1]=hr[1]*dAv+xv*b0.y;   y+=hr[1]*c0.y;
    hr[2]=hr[2]*dAv+xv*b0.z;   y+=hr[2]*c1.x;
    hr[3]=hr[3]*dAv+xv*b0.w;   y+=hr[3]*c1.y;
    hr[4]=hr[4]*dAv+xv*b1.x;   y+=hr[4]*c2v.x;
    hr[5]=hr[5]*dAv+xv*b1.y;   y+=hr[5]*c2v.y;
    hr[6]=hr[6]*dAv+xv*b1.z;   y+=hr[6]*c3.x;
    hr[7]=hr[7]*dAv+xv*b1.w;   y+=hr[7]*c3.y;
    hr[8]=hr[8]*dAv+xv*b2.x;   y+=hr[8]*c4.x;
    hr[9]=hr[9]*dAv+xv*b2.y;   y+=hr[9]*c4.y;
    hr[10]=hr[10]*dAv+xv*b2.z; y+=hr[10]*c5.x;
    hr[11]=hr[11]*dAv+xv*b2.w; y+=hr[11]*c5.y;
    hr[12]=hr[12]*dAv+xv*b3.x; y+=hr[12]*c6.x;
    hr[13]=hr[13]*dAv+xv*b3.y; y+=hr[13]*c6.y;
    hr[14]=hr[14]*dAv+xv*b3.z; y+=hr[14]*c7.x;
    hr[15]=hr[15]*dAv+xv*b3.w; y+=hr[15]*c7.y;
    yp[(size_t)s*DINNER] = __float2half(y);
  }
}

// ---------------- gate + RMS-norm -> fp16 ----------------
__global__ __launch_bounds__(128) void gate_kernel(const float* __restrict__ rms_w, int layer){
  __shared__ float sred[32];
  size_t row = blockIdx.x;
  int tid = threadIdx.x;
  float v[4]; float ss = 0.f;
  #pragma unroll
  for (int j=0;j<4;j++){
    int d = tid + j*128;
    float z = __half2float(g_zxh[row*DINPROJ + d]);
    float yv = __half2float(g_ybufh[row*DINNER + d]);
    float g = yv * siluf(z);
    v[j]=g; ss += g*g;
  }
  ss = blockReduceSum(ss, sred);
  float rstd = rsqrtf(ss*(1.0f/DINNER) + EPSV);
  #pragma unroll
  for (int j=0;j<4;j++){
    int d = tid + j*128;
    g_gah[row*DINNER + d] = __float2half(v[j]*rstd*rms_w[layer*DINNER + d]);
  }
}

// ---------------- residual + LayerNorm -> tok fp32 + fp16 ----------------
__global__ __launch_bounds__(256) void lnres_kernel(const float* __restrict__ lg, const float* __restrict__ lb, int layer){
  __shared__ float sred[32];
  size_t row = blockIdx.x; int d = threadIdx.x;
  float v = g_mproj[row*DM + d] + g_tok[row*DM + d];
  float mean = blockReduceSum(v, sred) * (1.0f/DM);
  float dv = v - mean;
  float var = blockReduceSum(dv*dv, sred) * (1.0f/DM);
  float o = dv*rsqrtf(var+EPSV)*lg[layer*DM+d] + lb[layer*DM+d];
  g_tok[row*DM + d] = o;
  g_th[row*DM + d] = __float2half(o);
}

// ---------------- grid-wide mean pool over L ----------------
__global__ __launch_bounds__(256) void pool_kernel(){
  __shared__ float s[256];
  int b = blockIdx.x >> 5, cg = blockIdx.x & 31;
  int colq = threadIdx.x & 7, lg = threadIdx.x >> 3;
  int col = cg*8 + colq;
  float acc = 0.f;
  for (int j=0;j<32;j++){
    int l = lg + j*32;
    acc += g_tok[((size_t)b*LSEQ + l)*DM + col];
  }
  s[threadIdx.x] = acc;
  __syncthreads();
  for (int off=16; off>0; off>>=1){
    if (lg < off) s[lg*8+colq] += s[(lg+off)*8+colq];
    __syncthreads();
  }
  if (lg == 0) g_pooled[b*DM + col] = s[colq]*(1.0f/LSEQ);
}

// ---------------- LN + head ----------------
__global__ __launch_bounds__(256) void head_kernel(const float* __restrict__ hg, const float* __restrict__ hb,
    const float* __restrict__ hw, const float* __restrict__ hbias, float* __restrict__ out){
  __shared__ float sred[32];
  __shared__ float sn[DM];
  int b = blockIdx.x, d = threadIdx.x;
  float pooled = g_pooled[b*DM + d];
  float mean = blockReduceSum(pooled, sred)*(1.0f/DM);
  float dv = pooled-mean;
  float var = blockReduceSum(dv*dv, sred)*(1.0f/DM);
  sn[d] = dv*rsqrtf(var+EPSV)*hg[d]+hb[d];
  __syncthreads();
  if (d < 10){
    float acc = hbias[d];
    for (int k=0;k<DM;k++) acc += sn[k]*hw[k*10+d];
    out[b*10+d] = acc;
  }
}

// ---------------- host launcher ----------------
extern "C" void kernel_launch(void* const* d_in, const int* in_sizes, int n_in,
                              void* d_out, int out_size)
{
  const float* x       = (const float*)d_in[0];
  const float* w1      = (const float*)d_in[1];
  const float* sg1     = (const float*)d_in[2];
  const float* sb1     = (const float*)d_in[3];
  const float* w2      = (const float*)d_in[4];
  const float* sg2     = (const float*)d_in[5];
  const float* sb2     = (const float*)d_in[6];
  const float* in_w    = (const float*)d_in[7];
  const float* conv_w  = (const float*)d_in[8];
  const float* conv_b  = (const float*)d_in[9];
  const float* dt_bias = (const float*)d_in[10];
  const float* A_log   = (const float*)d_in[11];
  const float* D_skip  = (const float*)d_in[12];
  const float* rms_w   = (const float*)d_in[13];
  const float* out_w   = (const float*)d_in[14];
  const float* ln_g    = (const float*)d_in[15];
  const float* ln_b    = (const float*)d_in[16];
  const float* hg      = (const float*)d_in[17];
  const float* hb      = (const float*)d_in[18];
  const float* hw      = (const float*)d_in[19];
  const float* hbias   = (const float*)d_in[20];
  float* out = (float*)d_out;

  cudaFuncSetAttribute(mmagemm_kernel, cudaFuncAttributeMaxDynamicSharedMemorySize, MMG_SMEM);
  cudaFuncSetAttribute(scan_fused_kernel, cudaFuncAttributeMaxDynamicSharedMemorySize, SCAN_SMEM);

  void *p;
  cudaGetSymbolAddress(&p, g_imh);   fp16* p_imh = (fp16*)p;
  cudaGetSymbolAddress(&p, g_w2h);   fp16* p_w2h = (fp16*)p;
  cudaGetSymbolAddress(&p, g_tok);   float* p_tok = (float*)p;
  cudaGetSymbolAddress(&p, g_th);    fp16* p_th = (fp16*)p;
  cudaGetSymbolAddress(&p, g_inwh);  fp16* p_inwh = (fp16*)p;
  cudaGetSymbolAddress(&p, g_owh);   fp16* p_owh = (fp16*)p;
  cudaGetSymbolAddress(&p, g_zxh);   fp16* p_zxh = (fp16*)p;
  cudaGetSymbolAddress(&p, g_dtraw); float* p_dtraw = (float*)p;
  cudaGetSymbolAddress(&p, g_gah);   fp16* p_gah = (fp16*)p;
  cudaGetSymbolAddress(&p, g_mproj); float* p_m = (float*)p;

  prep_inw<<<(4*NPAD_IN*DM)/256,256>>>(in_w);
  prep_outw<<<(4*DM*DINNER)/256,256>>>(out_w);
  prep_w2<<<(256*2048)/256,256>>>(w2);
  conv1_kernel<<<dim3(HWD,BATCH),256>>>(x, w1, sg1, sb1);

  mmagemm_kernel<<<dim3(2,128),256,MMG_SMEM>>>(p_imh, p_w2h,
      p_tok, 2048, 256, 256, 1, sg2, sb2, p_th);

  for (int i=0;i<4;i++){
    mmagemm_kernel<<<dim3(9,128),256,MMG_SMEM>>>(p_th,
        p_inwh + (size_t)i*NPAD_IN*DM,
        p_dtraw, DM, DINPROJ, DINPROJ, 2, (const float*)0, (const float*)0, p_zxh);
    dwdt_kernel<<<(NROWS*CONVDIM+255)/256,256>>>(conv_w, conv_b, i);
    scan_fused_kernel<<<128,512,SCAN_SMEM>>>(dt_bias, A_log, D_skip, i);
    gate_kernel<<<NROWS,128>>>(rms_w, i);
    mmagemm_kernel<<<dim3(2,128),256,MMG_SMEM>>>(p_gah,
        p_owh + (size_t)i*DM*DINNER,
        p_m, DINNER, DM, DM, 0, (const float*)0, (const float*)0, (fp16*)0);
    lnres_kernel<<<NROWS,256>>>(ln_g, ln_b, i);
  }

  pool_kernel<<<BATCH*32,256>>>();
  head_kernel<<<BATCH,256>>>(hg, hb, hw, hbias, out);
}

// round 17
// speedup vs baseline: 1.0661x; 1.0090x over previous
#include <cuda_runtime.h>
#include <cuda_fp16.h>
#include <math.h>
#include <stdint.h>

#define BATCH 8
#define HWD 128
#define C1 128
#define DM 256
#define LSEQ 1024
#define NROWS (BATCH*LSEQ)
#define DSTATE 16
#define HEADDIM 64
#define DINNER 512
#define NHEADS 8
#define CONVDIM 544
#define DINPROJ 1064
#define NPAD_IN 1152
#define NCHUNK 16
#define QCH 64
#define EPSV 1e-5f

typedef __half fp16;

// ---------------- scratch (device globals) ----------------
__device__ fp16  g_imh[(size_t)NROWS*2048];
__device__ fp16  g_w2h[256*2048];
__device__ float g_tok[NROWS*DM];
__device__ fp16  g_th[NROWS*DM];
__device__ fp16  g_inwh[4*NPAD_IN*DM];
__device__ fp16  g_owh[4*DM*DINNER];
__device__ fp16  g_zxh[(size_t)NROWS*DINPROJ];   // in_proj output, fp16
__device__ float g_dtraw[NROWS*NHEADS];          // fp32 side-channel for dt tail
__device__ fp16  g_xbch[(size_t)NROWS*CONVDIM];  // conv1d+silu output (fp16)
__device__ fp16  g_ybufh[(size_t)NROWS*DINNER];  // scan output (fp16)
__device__ fp16  g_gah[(size_t)NROWS*DINNER];
__device__ float g_mproj[NROWS*DM];
__device__ float g_pooled[BATCH*DM];

__device__ __forceinline__ float geluf(float t){ return 0.5f*t*(1.0f+erff(t*0.70710678118654752f)); }
__device__ __forceinline__ float siluf(float t){ return __fdividef(t, 1.0f + __expf(-t)); }

__device__ __forceinline__ float blockReduceSum(float v, float* sred){
  int lane = threadIdx.x & 31, wid = threadIdx.x >> 5;
  #pragma unroll
  for (int o=16;o>0;o>>=1) v += __shfl_xor_sync(0xffffffffu,v,o);
  if (lane==0) sred[wid]=v;
  __syncthreads();
  int nw = (blockDim.x+31)>>5;
  if (threadIdx.x < 32){
    float r = (threadIdx.x < nw) ? sred[threadIdx.x] : 0.f;
    #pragma unroll
    for (int o=16;o>0;o>>=1) r += __shfl_xor_sync(0xffffffffu,r,o);
    if (threadIdx.x==0) sred[0]=r;
  }
  __syncthreads();
  float r = sred[0];
  __syncthreads();
  return r;
}

// ---------------- mma/cp.async helpers ----------------
__device__ __forceinline__ uint32_t smem_u32(const void* p){
  uint32_t a;
  asm("{ .reg .u64 t; cvta.to.shared.u64 t, %1; cvt.u32.u64 %0, t; }" : "=r"(a) : "l"(p));
  return a;
}
__device__ __forceinline__ void ldsm4(uint32_t& a0,uint32_t& a1,uint32_t& a2,uint32_t& a3, uint32_t addr){
  asm volatile("ldmatrix.sync.aligned.m8n8.x4.shared.b16 {%0,%1,%2,%3}, [%4];"
    : "=r"(a0),"=r"(a1),"=r"(a2),"=r"(a3) : "r"(addr));
}
__device__ __forceinline__ void ldsm2(uint32_t& a0,uint32_t& a1, uint32_t addr){
  asm volatile("ldmatrix.sync.aligned.m8n8.x2.shared.b16 {%0,%1}, [%2];"
    : "=r"(a0),"=r"(a1) : "r"(addr));
}
__device__ __forceinline__ void mma16816(float* d, uint32_t a0,uint32_t a1,uint32_t a2,uint32_t a3,
                                         uint32_t b0,uint32_t b1){
  asm volatile("mma.sync.aligned.m16n8k16.row.col.f32.f16.f16.f32 "
    "{%0,%1,%2,%3}, {%4,%5,%6,%7}, {%8,%9}, {%0,%1,%2,%3};"
    : "+f"(d[0]),"+f"(d[1]),"+f"(d[2]),"+f"(d[3])
    : "r"(a0),"r"(a1),"r"(a2),"r"(a3),"r"(b0),"r"(b1));
}
__device__ __forceinline__ void cpasync16(uint32_t s, const void* g){
  asm volatile("cp.async.cg.shared.global [%0], [%1], 16;" :: "r"(s), "l"(g) : "memory");
}
__device__ __forceinline__ void cpcommit(){ asm volatile("cp.async.commit_group;" ::: "memory"); }
__device__ __forceinline__ void cpwait0(){ asm volatile("cp.async.wait_group 0;" ::: "memory"); }
__device__ __forceinline__ void cpwait1(){ asm volatile("cp.async.wait_group 1;" ::: "memory"); }

// ---------------- fp16 HMMA GEMM: C[M,N] = A[M,K] @ B^T ----------------
#define SPAD 72
#define ABUF (64*SPAD*2)
#define BBUF (128*SPAD*2)
#define STAGEB (ABUF+BBUF)
#define MMG_SMEM (2*STAGEB)
__global__ __launch_bounds__(256) void mmagemm_kernel(
    const fp16* __restrict__ A, const fp16* __restrict__ B,
    float* __restrict__ C, int K, int Nreal, int ldc, int epi,
    const float* __restrict__ eg, const float* __restrict__ eb,
    fp16* __restrict__ Cho)
{
  extern __shared__ char smem[];
  uint32_t sbase = smem_u32(smem);
  int tid = threadIdx.x, lane = tid & 31, wid = tid >> 5;
  int row0 = blockIdx.y<<6, col0 = blockIdx.x<<7;
  int warp_m = wid >> 2, warp_n = wid & 3;
  int m0w = warp_m*32, n0w = warp_n*32;

  int a_r[2], a_c[2];
  #pragma unroll
  for (int j=0;j<2;j++){ int id = tid + j*256; a_r[j]=id>>3; a_c[j]=(id&7)*8; }
  int b_r[4], b_c[4];
  #pragma unroll
  for (int j=0;j<4;j++){ int id = tid + j*256; b_r[j]=id>>3; b_c[j]=(id&7)*8; }

  uint32_t a_ld = (uint32_t)((m0w + (lane&7) + ((lane>>3)&1)*8)*SPAD*2 + (lane>>4)*16);
  uint32_t b_ld = (uint32_t)((n0w + (lane&7))*SPAD*2 + ((lane>>3)&1)*16);

  float d[2][4][4];
  #pragma unroll
  for (int i=0;i<2;i++)
    #pragma unroll
    for (int j=0;j<4;j++)
      #pragma unroll
      for (int q=0;q<4;q++) d[i][j][q]=0.f;

  int NC = K>>6;
  {
    uint32_t sa = sbase, sb = sbase + ABUF;
    #pragma unroll
    for (int j=0;j<2;j++) cpasync16(sa + (uint32_t)(a_r[j]*SPAD + a_c[j])*2,
                                    A + (size_t)(row0+a_r[j])*K + a_c[j]);
    #pragma unroll
    for (int j=0;j<4;j++) cpasync16(sb + (uint32_t)(b_r[j]*SPAD + b_c[j])*2,
                                    B + (size_t)(col0+b_r[j])*K + b_c[j]);
    cpcommit();
  }
  for (int c=0;c<NC;c++){
    if (c+1<NC){
      uint32_t sa = sbase + ((c+1)&1)*STAGEB, sb = sa + ABUF;
      int kof = (c+1)*64;
      #pragma unroll
      for (int j=0;j<2;j++) cpasync16(sa + (uint32_t)(a_r[j]*SPAD + a_c[j])*2,
                                      A + (size_t)(row0+a_r[j])*K + kof + a_c[j]);
      #pragma unroll
      for (int j=0;j<4;j++) cpasync16(sb + (uint32_t)(b_r[j]*SPAD + b_c[j])*2,
                                      B + (size_t)(col0+b_r[j])*K + kof + b_c[j]);
      cpcommit();
      cpwait1();
    } else {
      cpwait0();
    }
    __syncthreads();
    uint32_t uA = sbase + (c&1)*STAGEB;
    uint32_t uB = uA + ABUF;
    #pragma unroll
    for (int kk=0;kk<4;kk++){
      uint32_t b0[4], b1[4];
      #pragma unroll
      for (int j=0;j<4;j++)
        ldsm2(b0[j], b1[j], uB + b_ld + (uint32_t)(j*8*SPAD*2 + kk*32));
      #pragma unroll
      for (int i=0;i<2;i++){
        uint32_t x0,x1,x2,x3;
        ldsm4(x0,x1,x2,x3, uA + a_ld + (uint32_t)(i*16*SPAD*2 + kk*32));
        #pragma unroll
        for (int j=0;j<4;j++) mma16816(d[i][j], x0,x1,x2,x3, b0[j],b1[j]);
      }
    }
    __syncthreads();
  }

  float* stg = (float*)smem;
  #pragma unroll
  for (int i=0;i<2;i++){
    int r0 = m0w + i*16 + (lane>>2);
    #pragma unroll
    for (int j=0;j<4;j++){
      int c0 = n0w + j*8 + (lane&3)*2;
      *(float2*)&stg[r0*132 + c0]     = make_float2(d[i][j][0], d[i][j][1]);
      *(float2*)&stg[(r0+8)*132 + c0] = make_float2(d[i][j][2], d[i][j][3]);
    }
  }
  __syncthreads();

  #pragma unroll 1
  for (int q=0;q<8;q++){
    int e = q*256 + tid;
    int rr = e>>5, cc = (e&31)*4;
    float vx = stg[rr*132+cc+0], vy = stg[rr*132+cc+1];
    float vz = stg[rr*132+cc+2], vw = stg[rr*132+cc+3];
    int gcol = col0 + cc, grow = row0 + rr;
    if (epi==1){
      vx = geluf(vx*eg[gcol+0]+eb[gcol+0]);
      vy = geluf(vy*eg[gcol+1]+eb[gcol+1]);
      vz = geluf(vz*eg[gcol+2]+eb[gcol+2]);
      vw = geluf(vw*eg[gcol+3]+eb[gcol+3]);
      *(float4*)(C + (size_t)grow*ldc + gcol) = make_float4(vx,vy,vz,vw);
      __half2* ph = (__half2*)(Cho + (size_t)grow*ldc + gcol);
      ph[0] = __floats2half2_rn(vx,vy);
      ph[1] = __floats2half2_rn(vz,vw);
    } else if (epi==2){
      if (gcol + 4 <= Nreal){
        __half2* ph = (__half2*)(Cho + (size_t)grow*ldc + gcol);
        ph[0] = __floats2half2_rn(vx,vy);
        ph[1] = __floats2half2_rn(vz,vw);
        if (gcol >= 1056)
          *(float4*)(C + (size_t)grow*8 + (gcol-1056)) = make_float4(vx,vy,vz,vw);
      }
    } else {
      if (gcol < Nreal)
        *(float4*)(C + (size_t)grow*ldc + gcol) = make_float4(vx,vy,vz,vw);
    }
  }
}

// ---------------- weight prep ----------------
__global__ void prep_inw(const float* __restrict__ in_w){
  int idx = blockIdx.x*256 + threadIdx.x;
  int l = idx / (NPAD_IN*DM); int rem = idx % (NPAD_IN*DM);
  int n = rem / DM, k = rem % DM;
  float v = (n < DINPROJ) ? in_w[((size_t)l*DM + k)*DINPROJ + n] : 0.f;
  g_inwh[idx] = __float2half(v);
}
__global__ void prep_outw(const float* __restrict__ out_w){
  int idx = blockIdx.x*256 + threadIdx.x;
  int l = idx / (DM*DINNER); int rem = idx % (DM*DINNER);
  int n = rem / DINNER, k = rem % DINNER;
  g_owh[idx] = __float2half(out_w[((size_t)l*DINNER + k)*DM + n]);
}
__global__ void prep_w2(const float* __restrict__ w2){
  int idx = blockIdx.x*256 + threadIdx.x;
  g_w2h[idx] = __float2half(w2[idx]);
}

// ---------------- fused stem conv1 -> im2col fp16 (256 thr, padded-28 float4 weights) ----------------
__global__ __launch_bounds__(256) void conv1_kernel(const float* __restrict__ x,
    const float* __restrict__ w, const float* __restrict__ g1, const float* __restrict__ b1)
{
  __shared__ float swv[C1*28];
  __shared__ float sg[C1], sb[C1];
  __shared__ fp16 sstage[32][516];
  int tid = threadIdx.x;
  int xx = tid & 127, half = tid >> 7;
  int y = blockIdx.x, b = blockIdx.y;
  for (int i=tid;i<C1*27;i+=256){ int co=i/27, t=i-co*27; swv[co*28+t]=w[i]; }
  if (tid < C1){ sg[tid]=g1[tid]; sb[tid]=b1[tid]; }
  __syncthreads();
  float in[28];
  in[27] = 0.f;
  int q=0;
  #pragma unroll
  for (int ci=0;ci<3;ci++)
    #pragma unroll
    for (int ky=0;ky<3;ky++){
      int iy=y+ky-1;
      #pragma unroll
      for (int kx=0;kx<3;kx++){
        int ix=xx+kx-1;
        in[q++] = (iy>=0 && iy<HWD && ix>=0 && ix<HWD) ? x[((b*3+ci)*HWD+iy)*HWD+ix] : 0.f;
      }
    }
  int srow = xx>>2, scol = xx&3;
  int co0 = half*64;
  #pragma unroll 4
  for (int co=co0;co<co0+64;co++){
    const float4* wp = (const float4*)&swv[co*28];
    float acc=0.f;
    #pragma unroll
    for (int t=0;t<7;t++){
      float4 wv = wp[t];
      acc += in[t*4+0]*wv.x + in[t*4+1]*wv.y + in[t*4+2]*wv.z + in[t*4+3]*wv.w;
    }
    sstage[srow][co*4+scol] = __float2half(geluf(acc*sg[co]+sb[co]));
  }
  __syncthreads();
  int ky = y & 3;
  size_t rowbase = (size_t)b*LSEQ + (size_t)(y>>2)*32;
  #pragma unroll 4
  for (int t=0;t<16;t++){
    int id = tid + t*256;
    int r = id >> 7, ci = id & 127;
    *(uint2*)(g_imh + (rowbase + r)*2048 + ci*16 + ky*4) = *(uint2*)&sstage[r][ci*4];
  }
}

// ---------------- depthwise conv1d + silu (fp16 in, fp16 out) ----------------
__global__ void dwdt_kernel(const float* __restrict__ cw, const float* __restrict__ cb, int layer){
  int idx = blockIdx.x*256 + threadIdx.x;
  if (idx >= NROWS*CONVDIM) return;
  int c = idx % CONVDIM; int row = idx / CONVDIM;
  int l = row & 1023, b = row >> 10;
  const float* wp = cw + (layer*CONVDIM + c)*4;
  float acc = cb[layer*CONVDIM + c];
  const fp16* zcol = g_zxh + (size_t)(b<<10)*DINPROJ + 512 + c;
  #pragma unroll
  for (int k=0;k<4;k++){
    int ls = l + k - 3;
    if (ls >= 0) acc += __half2float(zcol[(size_t)ls*DINPROJ]) * wp[k];
  }
  g_xbch[(size_t)row*CONVDIM + c] = __float2half(siluf(acc));
}

// ---------------- fused SSM scan: grid 128 = (b,h,phalf), block 512 = (chunk, 32 p) ----------------
#define SCAN_SMEM (65536+32768+65536+32768+4096+4096+64)
__global__ __launch_bounds__(512,1) void scan_fused_kernel(
    const float* __restrict__ dt_bias, const float* __restrict__ A_log,
    const float* __restrict__ Dskip, int layer){
  extern __shared__ char smraw[];
  float* sB  = (float*)smraw;
  fp16*  sCh = (fp16*)(smraw + 65536);
  fp16*  sXh = (fp16*)(smraw + 98304);
  float* sS  = (float*)(smraw + 163840);
  float* sdA = (float*)(smraw + 196608);
  float* sdt = (float*)(smraw + 200704);
  float* sAc = (float*)(smraw + 204800);

  int tid = threadIdx.x;
  int bh = blockIdx.x >> 1, phalf = blockIdx.x & 1;
  int b = bh>>3, h = bh&7;
  int c = tid>>5, pl = tid&31;
  int p = phalf*32 + pl;

  const fp16* xbase = g_xbch + (size_t)b*LSEQ*CONVDIM;

  float aexp = __expf(A_log[layer*NHEADS+h]);
  float dtb  = dt_bias[layer*NHEADS+h];
  #pragma unroll
  for (int j=0;j<2;j++){
    int l = tid + j*512;
    float raw = g_dtraw[((size_t)b*LSEQ + l)*NHEADS + h] + dtb;
    float dt = (raw > 20.f) ? raw : __logf(1.0f + __expf(raw));
    sdt[l] = dt;
    sdA[l] = __expf(-aexp*dt);
  }
  #pragma unroll
  for (int j=0;j<32;j++){
    int id = tid + j*512;
    int l = id>>4, n = id&15;
    sB[id]  = __half2float(xbase[(size_t)l*CONVDIM + DINNER + n]);
    sCh[id] = xbase[(size_t)l*CONVDIM + DINNER + DSTATE + n];
  }
  {
    int chbase = h*HEADDIM + phalf*32;
    #pragma unroll
    for (int j=0;j<64;j++){
      int id = tid + j*512;
      int l = id>>5, pw = id&31;
      sXh[l*32 + pw] = xbase[(size_t)l*CONVDIM + chbase + pw];
    }
  }
  __syncthreads();

  if (pl == 0){
    float r = 1.f;
    #pragma unroll 4
    for (int s=0;s<QCH;s++) r *= sdA[c*QCH+s];
    sAc[c] = r;
  }

  int l0 = c*QCH;

  float hr[DSTATE];
  #pragma unroll
  for (int n=0;n<DSTATE;n++) hr[n]=0.f;
  #pragma unroll 4
  for (int s=0;s<QCH;s++){
    int l = l0+s;
    float xs = __half2float(sXh[l*32 + pl]);
    float xv = xs * sdt[l];
    float dAv = sdA[l];
    const float4* Bv = (const float4*)&sB[l*DSTATE];
    float4 b0=Bv[0], b1=Bv[1], b2=Bv[2], b3=Bv[3];
    hr[0]=hr[0]*dAv+xv*b0.x;  hr[1]=hr[1]*dAv+xv*b0.y;
    hr[2]=hr[2]*dAv+xv*b0.z;  hr[3]=hr[3]*dAv+xv*b0.w;
    hr[4]=hr[4]*dAv+xv*b1.x;  hr[5]=hr[5]*dAv+xv*b1.y;
    hr[6]=hr[6]*dAv+xv*b1.z;  hr[7]=hr[7]*dAv+xv*b1.w;
    hr[8]=hr[8]*dAv+xv*b2.x;  hr[9]=hr[9]*dAv+xv*b2.y;
    hr[10]=hr[10]*dAv+xv*b2.z;hr[11]=hr[11]*dAv+xv*b2.w;
    hr[12]=hr[12]*dAv+xv*b3.x;hr[13]=hr[13]*dAv+xv*b3.y;
    hr[14]=hr[14]*dAv+xv*b3.z;hr[15]=hr[15]*dAv+xv*b3.w;
  }
  #pragma unroll
  for (int n=0;n<DSTATE;n++) sS[c*512 + n*32 + pl] = hr[n];
  __syncthreads();

  {
    float run = 0.f;
    #pragma unroll
    for (int c2=0;c2<NCHUNK;c2++){
      float tmp = sS[c2*512 + tid];
      sS[c2*512 + tid] = run;
      run = run*sAc[c2] + tmp;
    }
  }
  __syncthreads();

  #pragma unroll
  for (int n=0;n<DSTATE;n++) hr[n] = sS[c*512 + n*32 + pl];
  float Dh = Dskip[layer*NHEADS+h];
  fp16* yp = g_ybufh + ((size_t)b*LSEQ + l0)*DINNER + h*HEADDIM + p;
  #pragma unroll 2
  for (int s=0;s<QCH;s++){
    int l = l0+s;
    float xs = __half2float(sXh[l*32 + pl]);
    float xv = xs * sdt[l];
    float dAv = sdA[l];
    const float4* Bv = (const float4*)&sB[l*DSTATE];
    const __half2* Ch = (const __half2*)&sCh[l*DSTATE];
    float4 b0=Bv[0], b1=Bv[1], b2=Bv[2], b3=Bv[3];
    float2 c0=__half22float2(Ch[0]), c1=__half22float2(Ch[1]);
    float2 c2v=__half22float2(Ch[2]), c3=__half22float2(Ch[3]);
    float2 c4=__half22float2(Ch[4]), c5=__half22float2(Ch[5]);
    float2 c6=__half22float2(Ch[6]), c7=__half22float2(Ch[7]);
    float y = xs*Dh;
    hr[0]=hr[0]*dAv+xv*b0.x;   y+=hr[0]*c0.x;
    hr[1]=hr[1]*dAv+xv*b0.y;   y+=hr[1]*c0.y;
    hr[2]=hr[2]*dAv+xv*b0.z;   y+=hr[2]*c1.x;
    hr[3]=hr[3]*dAv+xv*b0.w;   y+=hr[3]*c1.y;
    hr[4]=hr[4]*dAv+xv*b1.x;   y+=hr[4]*c2v.x;
    hr[5]=hr[5]*dAv+xv*b1.y;   y+=hr[5]*c2v.y;
    hr[6]=hr[6]*dAv+xv*b1.z;   y+=hr[6]*c3.x;
    hr[7]=hr[7]*dAv+xv*b1.w;   y+=hr[7]*c3.y;
    hr[8]=hr[8]*dAv+xv*b2.x;   y+=hr[8]*c4.x;
    hr[9]=hr[9]*dAv+xv*b2.y;   y+=hr[9]*c4.y;
    hr[10]=hr[10]*dAv+xv*b2.z; y+=hr[10]*c5.x;
    hr[11]=hr[11]*dAv+xv*b2.w; y+=hr[11]*c5.y;
    hr[12]=hr[12]*dAv+xv*b3.x; y+=hr[12]*c6.x;
    hr[13]=hr[13]*dAv+xv*b3.y; y+=hr[13]*c6.y;
    hr[14]=hr[14]*dAv+xv*b3.z; y+=hr[14]*c7.x;
    hr[15]=hr[15]*dAv+xv*b3.w; y+=hr[15]*c7.y;
    yp[(size_t)s*DINNER] = __float2half(y);
  }
}

// ---------------- gate + RMS-norm -> fp16 (vectorized half2 IO) ----------------
__global__ __launch_bounds__(128) void gate_kernel(const float* __restrict__ rms_w, int layer){
  __shared__ float sred[32];
  size_t row = blockIdx.x;
  int tid = threadIdx.x;
  int d0 = tid*4;
  __half2 zv0 = *(const __half2*)&g_zxh[row*DINPROJ + d0];
  __half2 zv1 = *(const __half2*)&g_zxh[row*DINPROJ + d0 + 2];
  __half2 yv0 = *(const __half2*)&g_ybufh[row*DINNER + d0];
  __half2 yv1 = *(const __half2*)&g_ybufh[row*DINNER + d0 + 2];
  float2 zf0 = __half22float2(zv0), zf1 = __half22float2(zv1);
  float2 yf0 = __half22float2(yv0), yf1 = __half22float2(yv1);
  float v[4];
  v[0] = yf0.x * siluf(zf0.x);
  v[1] = yf0.y * siluf(zf0.y);
  v[2] = yf1.x * siluf(zf1.x);
  v[3] = yf1.y * siluf(zf1.y);
  float ss = v[0]*v[0] + v[1]*v[1] + v[2]*v[2] + v[3]*v[3];
  ss = blockReduceSum(ss, sred);
  float rstd = rsqrtf(ss*(1.0f/DINNER) + EPSV);
  const float4 rw = *(const float4*)&rms_w[layer*DINNER + d0];
  __half2* go = (__half2*)&g_gah[row*DINNER + d0];
  go[0] = __floats2half2_rn(v[0]*rstd*rw.x, v[1]*rstd*rw.y);
  go[1] = __floats2half2_rn(v[2]*rstd*rw.z, v[3]*rstd*rw.w);
}

// ---------------- residual + LayerNorm -> tok fp32 + fp16 ----------------
__global__ __launch_bounds__(256) void lnres_kernel(const float* __restrict__ lg, const float* __restrict__ lb, int layer){
  __shared__ float sred[32];
  size_t row = blockIdx.x; int d = threadIdx.x;
  float v = g_mproj[row*DM + d] + g_tok[row*DM + d];
  float mean = blockReduceSum(v, sred) * (1.0f/DM);
  float dv = v - mean;
  float var = blockReduceSum(dv*dv, sred) * (1.0f/DM);
  float o = dv*rsqrtf(var+EPSV)*lg[layer*DM+d] + lb[layer*DM+d];
  g_tok[row*DM + d] = o;
  g_th[row*DM + d] = __float2half(o);
}

// ---------------- grid-wide mean pool over L ----------------
__global__ __launch_bounds__(256) void pool_kernel(){
  __shared__ float s[256];
  int b = blockIdx.x >> 5, cg = blockIdx.x & 31;
  int colq = threadIdx.x & 7, lg = threadIdx.x >> 3;
  int col = cg*8 + colq;
  float acc = 0.f;
  for (int j=0;j<32;j++){
    int l = lg + j*32;
    acc += g_tok[((size_t)b*LSEQ + l)*DM + col];
  }
  s[threadIdx.x] = acc;
  __syncthreads();
  for (int off=16; off>0; off>>=1){
    if (lg < off) s[lg*8+colq] += s[(lg+off)*8+colq];
    __syncthreads();
  }
  if (lg == 0) g_pooled[b*DM + col] = s[colq]*(1.0f/LSEQ);
}

// ---------------- LN + head ----------------
__global__ __launch_bounds__(256) void head_kernel(const float* __restrict__ hg, const float* __restrict__ hb,
    const float* __restrict__ hw, const float* __restrict__ hbias, float* __restrict__ out){
  __shared__ float sred[32];
  __shared__ float sn[DM];
  int b = blockIdx.x, d = threadIdx.x;
  float pooled = g_pooled[b*DM + d];
  float mean = blockReduceSum(pooled, sred)*(1.0f/DM);
  float dv = pooled-mean;
  float var = blockReduceSum(dv*dv, sred)*(1.0f/DM);
  sn[d] = dv*rsqrtf(var+EPSV)*hg[d]+hb[d];
  __syncthreads();
  if (d < 10){
    float acc = hbias[d];
    for (int k=0;k<DM;k++) acc += sn[k]*hw[k*10+d];
    out[b*10+d] = acc;
  }
}

// ---------------- host launcher ----------------
extern "C" void kernel_launch(void* const* d_in, const int* in_sizes, int n_in,
                              void* d_out, int out_size)
{
  const float* x       = (const float*)d_in[0];
  const float* w1      = (const float*)d_in[1];
  const float* sg1     = (const float*)d_in[2];
  const float* sb1     = (const float*)d_in[3];
  const float* w2      = (const float*)d_in[4];
  const float* sg2     = (const float*)d_in[5];
  const float* sb2     = (const float*)d_in[6];
  const float* in_w    = (const float*)d_in[7];
  const float* conv_w  = (const float*)d_in[8];
  const float* conv_b  = (const float*)d_in[9];
  const float* dt_bias = (const float*)d_in[10];
  const float* A_log   = (const float*)d_in[11];
  const float* D_skip  = (const float*)d_in[12];
  const float* rms_w   = (const float*)d_in[13];
  const float* out_w   = (const float*)d_in[14];
  const float* ln_g    = (const float*)d_in[15];
  const float* ln_b    = (const float*)d_in[16];
  const float* hg      = (const float*)d_in[17];
  const float* hb      = (const float*)d_in[18];
  const float* hw      = (const float*)d_in[19];
  const float* hbias   = (const float*)d_in[20];
  float* out = (float*)d_out;

  cudaFuncSetAttribute(mmagemm_kernel, cudaFuncAttributeMaxDynamicSharedMemorySize, MMG_SMEM);
  cudaFuncSetAttribute(scan_fused_kernel, cudaFuncAttributeMaxDynamicSharedMemorySize, SCAN_SMEM);

  void *p;
  cudaGetSymbolAddress(&p, g_imh);   fp16* p_imh = (fp16*)p;
  cudaGetSymbolAddress(&p, g_w2h);   fp16* p_w2h = (fp16*)p;
  cudaGetSymbolAddress(&p, g_tok);   float* p_tok = (float*)p;
  cudaGetSymbolAddress(&p, g_th);    fp16* p_th = (fp16*)p;
  cudaGetSymbolAddress(&p, g_inwh);  fp16* p_inwh = (fp16*)p;
  cudaGetSymbolAddress(&p, g_owh);   fp16* p_owh = (fp16*)p;
  cudaGetSymbolAddress(&p, g_zxh);   fp16* p_zxh = (fp16*)p;
  cudaGetSymbolAddress(&p, g_dtraw); float* p_dtraw = (float*)p;
  cudaGetSymbolAddress(&p, g_gah);   fp16* p_gah = (fp16*)p;
  cudaGetSymbolAddress(&p, g_mproj); float* p_m = (float*)p;

  prep_inw<<<(4*NPAD_IN*DM)/256,256>>>(in_w);
  prep_outw<<<(4*DM*DINNER)/256,256>>>(out_w);
  prep_w2<<<(256*2048)/256,256>>>(w2);
  conv1_kernel<<<dim3(HWD,BATCH),256>>>(x, w1, sg1, sb1);

  mmagemm_kernel<<<dim3(2,128),256,MMG_SMEM>>>(p_imh, p_w2h,
      p_tok, 2048, 256, 256, 1, sg2, sb2, p_th);

  for (int i=0;i<4;i++){
    mmagemm_kernel<<<dim3(9,128),256,MMG_SMEM>>>(p_th,
        p_inwh + (size_t)i*NPAD_IN*DM,
        p_dtraw, DM, DINPROJ, DINPROJ, 2, (const float*)0, (const float*)0, p_zxh);
    dwdt_kernel<<<(NROWS*CONVDIM+255)/256,256>>>(conv_w, conv_b, i);
    scan_fused_kernel<<<128,512,SCAN_SMEM>>>(dt_bias, A_log, D_skip, i);
    gate_kernel<<<NROWS,128>>>(rms_w, i);
    mmagemm_kernel<<<dim3(2,128),256,MMG_SMEM>>>(p_gah,
        p_owh + (size_t)i*DM*DINNER,
        p_m, DINNER, DM, DM, 0, (const float*)0, (const float*)0, (fp16*)0);
    lnres_kernel<<<NROWS,256>>>(ln_g, ln_b, i);
  }

  pool_kernel<<<BATCH*32,256>>>();
  head_kernel<<<BATCH,256>>>(hg, hb, hw, hbias, out);
}